// round 4
// baseline (speedup 1.0000x reference)
#include <cuda_runtime.h>
#include <cstdint>

#define NN 100000
#define NE 1600000
#define DIM 128

typedef unsigned long long u64;

// ---------------------------------------------------------------------------
// Scratch (__device__ globals: allocation-free rule)
// ---------------------------------------------------------------------------
__device__ float g_h1[NN * DIM];
__device__ float g_h2[NN * DIM];
__device__ int   g_deg[NN];
__device__ int   g_rowstart[NN];
__device__ int   g_cursor[NN];
__device__ int   g_csrsrc[NE];
__device__ int   g_bsum[128];

// ---------------------------------------------------------------------------
// f32x2 helpers (Blackwell packed fp32 FMA)
// ---------------------------------------------------------------------------
__device__ __forceinline__ u64 dup2(float v) {
    u64 r; asm("mov.b64 %0, {%1, %1};" : "=l"(r) : "f"(v)); return r;
}
__device__ __forceinline__ float2 unpack2(u64 v) {
    float2 p; asm("mov.b64 {%0, %1}, %2;" : "=f"(p.x), "=f"(p.y) : "l"(v)); return p;
}
__device__ __forceinline__ void ffma2(u64& d, u64 a, u64 b) {
    asm("fma.rn.f32x2 %0, %1, %2, %0;" : "+l"(d) : "l"(a), "l"(b));
}

// ---------------------------------------------------------------------------
// CSR build kernels
// ---------------------------------------------------------------------------
__global__ void k_zero_int(int* __restrict__ p, int n) {
    int i = blockIdx.x * blockDim.x + threadIdx.x;
    if (i < n) p[i] = 0;
}

__global__ void k_hist(const int* __restrict__ dst) {
    int e = blockIdx.x * blockDim.x + threadIdx.x;
    if (e < NE) atomicAdd(&g_deg[dst[e]], 1);
}

// per-1024-chunk degree sums
__global__ void k_blocksum() {
    __shared__ int sh[256];
    int base = blockIdx.x * 1024;
    int s = 0;
    for (int j = threadIdx.x; j < 1024; j += 256) {
        int i = base + j;
        if (i < NN) s += g_deg[i];
    }
    sh[threadIdx.x] = s; __syncthreads();
    for (int o = 128; o > 0; o >>= 1) {
        if (threadIdx.x < o) sh[threadIdx.x] += sh[threadIdx.x + o];
        __syncthreads();
    }
    if (threadIdx.x == 0) g_bsum[blockIdx.x] = sh[0];
}

// fused: block base (masked sum of bsums) + local exclusive scan + write
__global__ void k_scan2() {
    __shared__ int sh[256];
    __shared__ int sbase;
    int tid = threadIdx.x;

    int v = (tid < blockIdx.x) ? g_bsum[tid] : 0;   // blockIdx.x <= 97 < 256
    sh[tid] = v; __syncthreads();
    for (int o = 128; o > 0; o >>= 1) {
        if (tid < o) sh[tid] += sh[tid + o];
        __syncthreads();
    }
    if (tid == 0) sbase = sh[0];
    __syncthreads();

    int base = blockIdx.x * 1024 + tid * 4;
    int d[4]; int s = 0;
#pragma unroll
    for (int j = 0; j < 4; ++j) {
        int i = base + j;
        d[j] = (i < NN) ? g_deg[i] : 0;
        s += d[j];
    }
    sh[tid] = s; __syncthreads();
    for (int o = 1; o < 256; o <<= 1) {
        int t = (tid >= o) ? sh[tid - o] : 0;
        __syncthreads();
        sh[tid] += t;
        __syncthreads();
    }
    int off = sbase + sh[tid] - s;
#pragma unroll
    for (int j = 0; j < 4; ++j) {
        int i = base + j;
        if (i < NN) { g_rowstart[i] = off; g_cursor[i] = off; off += d[j]; }
    }
}

__global__ void k_bucket(const int* __restrict__ src, const int* __restrict__ dst) {
    int e = blockIdx.x * blockDim.x + threadIdx.x;
    if (e < NE) {
        int pos = atomicAdd(&g_cursor[dst[e]], 1);
        g_csrsrc[pos] = src[e];
    }
}

// ---------------------------------------------------------------------------
// FUSED SAGE layer: aggregation + dual GEMM + bias + activation
//   out[n,:] = act( mean_{j in N(n)} hin[j,:] @ Wl + hin[n,:] @ Wr + b )
//
// Block = 128 threads, tile 64 nodes x 128 dims.
// Phase A (smem fill 0): warp w pull-aggregates nodes w*16..w*16+15 directly
//   into the smem tile (register float4 accum per lane, deg_inv folded) —
//   no global mean buffer exists at all.
// Phase B: FFMA2 over smem vs Wl.
// Phase C (smem fill 1): stage hin tile; Phase D: FFMA2 vs Wr.
// smem stride 132 floats (16B-aligned rows; warp's two ty rows 4 banks apart).
// ---------------------------------------------------------------------------
template <bool RELU>
__global__ void __launch_bounds__(128, 4)
k_sage(const float* __restrict__ hin,
       const float* __restrict__ Wl,
       const float* __restrict__ Wr,
       const float* __restrict__ bias,
       float* __restrict__ out) {
    constexpr int ROWS = 64;
    constexpr int STR  = DIM + 4;   // 132
    __shared__ float s_in[ROWS * STR];

    const int tx   = threadIdx.x & 15;
    const int ty   = threadIdx.x >> 4;
    const int warp = threadIdx.x >> 5;
    const int lane = threadIdx.x & 31;
    const int row0 = blockIdx.x * ROWS;

    u64 acc[8][4];
#pragma unroll
    for (int i = 0; i < 8; ++i)
#pragma unroll
        for (int j = 0; j < 4; ++j) acc[i][j] = 0ull;

    const float4* xv = (const float4*)hin;

#pragma unroll
    for (int phase = 0; phase < 2; ++phase) {
        const float* W = phase ? Wr : Wl;

        __syncthreads();  // prior phase's smem reads complete
        if (phase == 0) {
            // Phase A: aggregate 16 nodes per warp into smem
            for (int i = 0; i < 16; ++i) {
                int r    = warp * 16 + i;
                int node = row0 + r;
                float4 a = make_float4(0.f, 0.f, 0.f, 0.f);
                if (node < NN) {
                    int beg = __ldg(g_rowstart + node);
                    int d   = __ldg(g_deg + node);
                    int end = beg + d;
                    for (int e = beg; e < end; e += 8) {
                        int idx[8];
#pragma unroll
                        for (int j = 0; j < 8; ++j)
                            idx[j] = (e + j < end) ? __ldg(g_csrsrc + e + j) : -1;
#pragma unroll
                        for (int j = 0; j < 8; ++j) {
                            if (idx[j] >= 0) {
                                float4 v = __ldg(xv + (size_t)idx[j] * 32 + lane);
                                a.x += v.x; a.y += v.y; a.z += v.z; a.w += v.w;
                            }
                        }
                    }
                    float inv = (d > 0) ? (1.0f / (float)d) : 0.0f;
                    a.x *= inv; a.y *= inv; a.z *= inv; a.w *= inv;
                }
                *(float4*)(s_in + r * STR + lane * 4) = a;
            }
        } else {
            // Phase C: stage hin tile directly
            for (int t = threadIdx.x; t < ROWS * 32; t += 128) {
                int r  = t >> 5;
                int c4 = t & 31;
                int grow = row0 + r;
                float4 v = make_float4(0.f, 0.f, 0.f, 0.f);
                if (grow < NN)
                    v = __ldg(((const float4*)(hin + (size_t)grow * DIM)) + c4);
                *(float4*)(s_in + r * STR + c4 * 4) = v;
            }
        }
        __syncthreads();

        const u64* Wp = (const u64*)W;  // Wp[k*64 + c] = (W[k][2c], W[k][2c+1])
#pragma unroll 4
        for (int k = 0; k < DIM; ++k) {
            u64 w0 = __ldg(Wp + k * 64 + tx * 4 + 0);
            u64 w1 = __ldg(Wp + k * 64 + tx * 4 + 1);
            u64 w2 = __ldg(Wp + k * 64 + tx * 4 + 2);
            u64 w3 = __ldg(Wp + k * 64 + tx * 4 + 3);
            u64 sv[8];
#pragma unroll
            for (int i = 0; i < 8; ++i) sv[i] = dup2(s_in[(ty + 8 * i) * STR + k]);
#pragma unroll
            for (int i = 0; i < 8; ++i) {
                ffma2(acc[i][0], sv[i], w0);
                ffma2(acc[i][1], sv[i], w1);
                ffma2(acc[i][2], sv[i], w2);
                ffma2(acc[i][3], sv[i], w3);
            }
        }
    }

    // epilogue
    float4 b0 = __ldg((const float4*)(bias + tx * 8));
    float4 b1 = __ldg((const float4*)(bias + tx * 8) + 1);

#pragma unroll
    for (int i = 0; i < 8; ++i) {
        int grow = row0 + ty + i * 8;
        if (grow >= NN) continue;
        float2 p0 = unpack2(acc[i][0]);
        float2 p1 = unpack2(acc[i][1]);
        float2 p2 = unpack2(acc[i][2]);
        float2 p3 = unpack2(acc[i][3]);
        float4 o0 = make_float4(p0.x + b0.x, p0.y + b0.y, p1.x + b0.z, p1.y + b0.w);
        float4 o1 = make_float4(p2.x + b1.x, p2.y + b1.y, p3.x + b1.z, p3.y + b1.w);
        if (RELU) {
            o0.x = fmaxf(o0.x, 0.f); o0.y = fmaxf(o0.y, 0.f);
            o0.z = fmaxf(o0.z, 0.f); o0.w = fmaxf(o0.w, 0.f);
            o1.x = fmaxf(o1.x, 0.f); o1.y = fmaxf(o1.y, 0.f);
            o1.z = fmaxf(o1.z, 0.f); o1.w = fmaxf(o1.w, 0.f);
        }
        float* op = out + (size_t)grow * DIM + tx * 8;
        *(float4*)(op)     = o0;
        *(float4*)(op + 4) = o1;
    }
}

// ---------------------------------------------------------------------------
// kernel_launch
// inputs: t, x, edge_index, W1_l, W1_r, b1, W2_l, W2_r, b2, W3_l, W3_r, b3
// ---------------------------------------------------------------------------
extern "C" void kernel_launch(void* const* d_in, const int* in_sizes, int n_in,
                              void* d_out, int out_size) {
    const float* x   = (const float*)d_in[1];
    const int*   ei  = (const int*)d_in[2];
    const int*   src = ei;
    const int*   dst = ei + NE;
    const float* W1l = (const float*)d_in[3];
    const float* W1r = (const float*)d_in[4];
    const float* b1  = (const float*)d_in[5];
    const float* W2l = (const float*)d_in[6];
    const float* W2r = (const float*)d_in[7];
    const float* b2  = (const float*)d_in[8];
    const float* W3l = (const float*)d_in[9];
    const float* W3r = (const float*)d_in[10];
    const float* b3  = (const float*)d_in[11];
    float* out = (float*)d_out;

    float *h1, *h2;
    cudaGetSymbolAddress((void**)&h1, g_h1);
    cudaGetSymbolAddress((void**)&h2, g_h2);
    int* deg;
    cudaGetSymbolAddress((void**)&deg, g_deg);

    const int NB_SCAN     = (NN + 1023) / 1024;   // 98
    const int SAGE_BLOCKS = (NN + 63) / 64;

    // CSR build
    k_zero_int<<<(NN + 255) / 256, 256>>>(deg, NN);
    k_hist<<<(NE + 255) / 256, 256>>>(dst);
    k_blocksum<<<NB_SCAN, 256>>>();
    k_scan2<<<NB_SCAN, 256>>>();
    k_bucket<<<(NE + 255) / 256, 256>>>(src, dst);

    // fused layers (launch 5 = layer-1 k_sage -> ncu target)
    k_sage<true><<<SAGE_BLOCKS, 128>>>(x,  W1l, W1r, b1, h1);
    k_sage<true><<<SAGE_BLOCKS, 128>>>(h1, W2l, W2r, b2, h2);
    k_sage<false><<<SAGE_BLOCKS, 128>>>(h2, W3l, W3r, b3, out);
}